// round 15
// baseline (speedup 1.0000x reference)
#include <cuda_runtime.h>
#include <cuda_fp16.h>
#include <cstdint>

// Problem dims (fixed by the reference)
#define S_ 2048
#define B_ 2
#define E_ 1024
#define H_ 16
#define DH_ 64
#define M_ (S_ * B_)
#define SCALING_ 0.125f
#define LOG2E_ 1.4426950408889634f

// ---------------------------------------------------------------------------
// Scratch (allocation-free rule: __device__ globals), all fp16
// ---------------------------------------------------------------------------
__device__ __half g_hx[(size_t)M_ * E_];
__device__ __half g_hwq[(size_t)E_ * E_];
__device__ __half g_hwk[(size_t)E_ * E_];
__device__ __half g_hwv[(size_t)E_ * E_];
__device__ __half g_hwo[(size_t)E_ * E_];
__device__ __half g_q[(size_t)M_ * E_];      // (scaling*log2e)-prescaled Q
__device__ __half g_k[(size_t)M_ * E_];
__device__ __half g_vt[(size_t)M_ * E_];     // V transposed: [b][h][d][s]
__device__ __half g_ctx[(size_t)M_ * E_];

// ---------------------------------------------------------------------------
// Helpers (.target sm_103 safe)
// ---------------------------------------------------------------------------
__device__ __forceinline__ uint32_t smem_u32(const void* p) {
    uint32_t a;
    asm("{ .reg .u64 t; cvta.to.shared.u64 t, %1; cvt.u32.u64 %0, t; }"
        : "=r"(a) : "l"(p));
    return a;
}

__device__ __forceinline__ uint32_t pack_h2(float a, float b) {
    __half2 h = __floats2half2_rn(a, b);
    return *reinterpret_cast<uint32_t*>(&h);
}

__device__ __forceinline__ void ldsm_x4(uint32_t addr, uint32_t& r0, uint32_t& r1,
                                        uint32_t& r2, uint32_t& r3) {
    asm volatile("ldmatrix.sync.aligned.m8n8.x4.shared.b16 {%0,%1,%2,%3}, [%4];"
                 : "=r"(r0), "=r"(r1), "=r"(r2), "=r"(r3) : "r"(addr));
}

__device__ __forceinline__ void mma_f16(float* d, const uint32_t* a, const uint32_t* b) {
    asm volatile(
        "mma.sync.aligned.m16n8k16.row.col.f32.f16.f16.f32 "
        "{%0,%1,%2,%3}, {%4,%5,%6,%7}, {%8,%9}, {%0,%1,%2,%3};"
        : "+f"(d[0]), "+f"(d[1]), "+f"(d[2]), "+f"(d[3])
        : "r"(a[0]), "r"(a[1]), "r"(a[2]), "r"(a[3]), "r"(b[0]), "r"(b[1]));
}

#define CP_ASYNC16(dst, src) \
    asm volatile("cp.async.cg.shared.global [%0], [%1], 16;" \
                 :: "r"(dst), "l"(src) : "memory")
#define CP_COMMIT() asm volatile("cp.async.commit_group;" ::: "memory")
#define CP_WAIT1()  asm volatile("cp.async.wait_group 1;" ::: "memory")
#define CP_WAIT2()  asm volatile("cp.async.wait_group 2;" ::: "memory")
#define CP_WAIT0()  asm volatile("cp.async.wait_group 0;" ::: "memory")

__device__ __forceinline__ uint32_t sw128(uint32_t off) {
    return off ^ ((off >> 3) & 0x70);
}

// ---------------------------------------------------------------------------
// Batched fp32 -> fp16 convert
// ---------------------------------------------------------------------------
#define XN4 (M_ * E_ / 4)
#define WN4 (E_ * E_ / 4)

__global__ __launch_bounds__(256)
void cvt_all_f16(const float* __restrict__ x,
                 const float* __restrict__ w0, const float* __restrict__ w1,
                 const float* __restrict__ w2, const float* __restrict__ w3,
                 __half* __restrict__ hx,
                 __half* __restrict__ h0, __half* __restrict__ h1,
                 __half* __restrict__ h2, __half* __restrict__ h3)
{
    int i = blockIdx.x * blockDim.x + threadIdx.x;
    const float* src;
    __half* dst;
    int j;
    if (i < XN4)                { src = x;  dst = hx; j = i; }
    else if (i < XN4 + WN4)     { src = w0; dst = h0; j = i - XN4; }
    else if (i < XN4 + 2 * WN4) { src = w1; dst = h1; j = i - XN4 - WN4; }
    else if (i < XN4 + 3 * WN4) { src = w2; dst = h2; j = i - XN4 - 2 * WN4; }
    else                        { src = w3; dst = h3; j = i - XN4 - 3 * WN4; }
    float4 v = ((const float4*)src)[j];
    uint2 o;
    o.x = pack_h2(v.x, v.y);
    o.y = pack_h2(v.z, v.w);
    ((uint2*)dst)[j] = o;
}

// ---------------------------------------------------------------------------
// fp16 mma GEMM (NT) — R7 warp layout + 3-stage cp.async ring (R14-validated).
// CTA 128x128, BK=64 halfs, 3 smem stages (96 KB), occ 2.
// mode 0: fp32 out; 1: half out; 2: half transposed out [b][h][d][s].
// ---------------------------------------------------------------------------
#define GK 1024
#define BKH 64
#define NCH (GK / BKH)            // 16
#define OPB (128 * 128)           // 16 KB per operand per stage
#define GEMM_SMEM (6 * OPB)       // 96 KB: A0 B0 A1 B1 A2 B2

__device__ __forceinline__
void gemm_body(const __half* __restrict__ A, const __half* __restrict__ W,
               const float* __restrict__ bias, void* __restrict__ Cout,
               float alpha, int mode, char* smg, int bx, int by)
{
    const uint32_t sb = smem_u32(smg);
    const uint32_t aB[3] = { sb,            sb + 2 * OPB, sb + 4 * OPB };
    const uint32_t bB[3] = { sb + OPB,      sb + 3 * OPB, sb + 5 * OPB };

    const int tid = threadIdx.x;          // 256 threads
    const int wid = tid >> 5;             // 0..7
    const int lane = tid & 31;
    const int warp_m = wid & 1;           // *64
    const int warp_n = wid >> 1;          // *32

    const __half* Ap = A + (size_t)(by * 128) * GK;
    const __half* Wp = W + (size_t)(bx * 128) * GK;

    const int ldrow = tid >> 3;
    const int ldc16 = tid & 7;

    const int a_hi = (lane & 16) ? 1 : 0;
    const int b_row_rel = (lane & 7) + ((lane & 16) >> 1);
    const int b_hi = (lane & 8) ? 1 : 0;

    float acc[4][4][4];
#pragma unroll
    for (int i = 0; i < 4; ++i)
#pragma unroll
        for (int j = 0; j < 4; ++j)
#pragma unroll
            for (int r = 0; r < 4; ++r) acc[i][j][r] = 0.0f;

    auto issue = [&](int c, int buf) {
#pragma unroll
        for (int i = 0; i < 4; ++i) {
            int row = ldrow + i * 32;
            uint32_t sw = sw128((uint32_t)(row * 128 + ldc16 * 16));
            const __half* ga = Ap + (size_t)row * GK + c * BKH + ldc16 * 8;
            const __half* gw = Wp + (size_t)row * GK + c * BKH + ldc16 * 8;
            CP_ASYNC16(aB[buf] + sw, ga);
            CP_ASYNC16(bB[buf] + sw, gw);
        }
    };

    issue(0, 0); CP_COMMIT();
    issue(1, 1); CP_COMMIT();
    issue(2, 2); CP_COMMIT();

    int buf = 0;
    for (int c = 0; c < NCH; ++c) {
        CP_WAIT2();            // chunk c landed (up to 2 groups still pending)
        __syncthreads();

#pragma unroll
        for (int s = 0; s < 4; ++s) {
            uint32_t bfr[4][2];
#pragma unroll
            for (int nfp = 0; nfp < 2; ++nfp) {
                int row = warp_n * 32 + nfp * 16 + b_row_rel;
                uint32_t off = (uint32_t)(row * 128 + (2 * s + b_hi) * 16);
                uint32_t r0, r1, r2, r3;
                ldsm_x4(bB[buf] + sw128(off), r0, r1, r2, r3);
                bfr[2 * nfp + 0][0] = r0; bfr[2 * nfp + 0][1] = r1;
                bfr[2 * nfp + 1][0] = r2; bfr[2 * nfp + 1][1] = r3;
            }
#pragma unroll
            for (int mf = 0; mf < 4; ++mf) {
                int row = warp_m * 64 + mf * 16 + (lane & 15);
                uint32_t off = (uint32_t)(row * 128 + (2 * s + a_hi) * 16);
                uint32_t af[4];
                ldsm_x4(aB[buf] + sw128(off), af[0], af[1], af[2], af[3]);
#pragma unroll
                for (int nf = 0; nf < 4; ++nf)
                    mma_f16(acc[mf][nf], af, bfr[nf]);
            }
        }
        __syncthreads();       // all warps done reading this stage
        if (c + 3 < NCH) issue(c + 3, buf);
        CP_COMMIT();
        buf = (buf == 2) ? 0 : buf + 1;
    }

    const int gq = lane >> 2;
    const int tg = lane & 3;

    if (mode == 0) {
        float* C = (float*)Cout;
#pragma unroll
        for (int nf = 0; nf < 4; ++nf) {
            const int col = bx * 128 + warp_n * 32 + nf * 8 + 2 * tg;
            const float bv0 = bias[col], bv1 = bias[col + 1];
#pragma unroll
            for (int mf = 0; mf < 4; ++mf) {
                const int r0 = by * 128 + warp_m * 64 + mf * 16 + gq;
                float2 lo, hi;
                lo.x = alpha * (acc[mf][nf][0] + bv0);
                lo.y = alpha * (acc[mf][nf][1] + bv1);
                hi.x = alpha * (acc[mf][nf][2] + bv0);
                hi.y = alpha * (acc[mf][nf][3] + bv1);
                *(float2*)(C + (size_t)r0 * E_ + col) = lo;
                *(float2*)(C + (size_t)(r0 + 8) * E_ + col) = hi;
            }
        }
        return;
    }
    if (mode == 1) {
        __half* C = (__half*)Cout;
#pragma unroll
        for (int nf = 0; nf < 4; ++nf) {
            const int col = bx * 128 + warp_n * 32 + nf * 8 + 2 * tg;
            const float bv0 = bias[col], bv1 = bias[col + 1];
#pragma unroll
            for (int mf = 0; mf < 4; ++mf) {
                const int r0 = by * 128 + warp_m * 64 + mf * 16 + gq;
                uint32_t lo = pack_h2(alpha * (acc[mf][nf][0] + bv0),
                                      alpha * (acc[mf][nf][1] + bv1));
                uint32_t hi = pack_h2(alpha * (acc[mf][nf][2] + bv0),
                                      alpha * (acc[mf][nf][3] + bv1));
                *(uint32_t*)(C + (size_t)r0 * E_ + col) = lo;
                *(uint32_t*)(C + (size_t)(r0 + 8) * E_ + col) = hi;
            }
        }
        return;
    }

    // mode 2: transposed epilogue -> Cvt[b][h][d][s] as half
    CP_WAIT0();
    __syncthreads();
    float* Cs = (float*)smg;     // [128][132]
#pragma unroll
    for (int nf = 0; nf < 4; ++nf) {
        const int colL = warp_n * 32 + nf * 8 + 2 * tg;
        const int colG = bx * 128 + colL;
        const float bv0 = bias[colG], bv1 = bias[colG + 1];
#pragma unroll
        for (int mf = 0; mf < 4; ++mf) {
            const int r0 = warp_m * 64 + mf * 16 + gq;
            Cs[r0 * 132 + colL]           = acc[mf][nf][0] + bv0;
            Cs[r0 * 132 + colL + 1]       = acc[mf][nf][1] + bv1;
            Cs[(r0 + 8) * 132 + colL]     = acc[mf][nf][2] + bv0;
            Cs[(r0 + 8) * 132 + colL + 1] = acc[mf][nf][3] + bv1;
        }
    }
    __syncthreads();
    {
        __half* C = (__half*)Cout;
        const int col = tid >> 1;
        const int b = tid & 1;
        const int h = bx * 2 + (col >> 6);
        const int d = col & 63;
        __half* dst = C + ((size_t)(b * H_ + h) * DH_ + d) * S_ + by * 64;
#pragma unroll
        for (int j = 0; j < 16; ++j) {
            uint2 o;
            o.x = pack_h2(Cs[((4 * j + 0) * 2 + b) * 132 + col],
                          Cs[((4 * j + 1) * 2 + b) * 132 + col]);
            o.y = pack_h2(Cs[((4 * j + 2) * 2 + b) * 132 + col],
                          Cs[((4 * j + 3) * 2 + b) * 132 + col]);
            *(uint2*)(dst + 4 * j) = o;
        }
    }
}

// fused QKV: z = 0 -> Q (alpha = SCALING*LOG2E, half out), 1 -> K, 2 -> Vt
__global__ __launch_bounds__(256, 2)
void gemm_qkv_f16(const __half* __restrict__ A,
                  const __half* __restrict__ Wq, const __half* __restrict__ Wk,
                  const __half* __restrict__ Wv,
                  const float* __restrict__ bq, const float* __restrict__ bk,
                  const float* __restrict__ bv,
                  __half* __restrict__ Q, __half* __restrict__ K,
                  __half* __restrict__ Vt)
{
    extern __shared__ __align__(128) char smg[];
    const int z = blockIdx.z;
    const __half* W = (z == 0) ? Wq : (z == 1) ? Wk : Wv;
    const float* bias = (z == 0) ? bq : (z == 1) ? bk : bv;
    void* C = (z == 0) ? (void*)Q : (z == 1) ? (void*)K : (void*)Vt;
    const float alpha = (z == 0) ? SCALING_ * LOG2E_ : 1.0f;
    const int mode = (z == 2) ? 2 : 1;
    gemm_body(A, W, bias, C, alpha, mode, smg, blockIdx.x, blockIdx.y);
}

__global__ __launch_bounds__(256, 2)
void gemm_out_f16(const __half* __restrict__ A, const __half* __restrict__ W,
                  const float* __restrict__ bias, float* __restrict__ C)
{
    extern __shared__ __align__(128) char smg[];
    gemm_body(A, W, bias, C, 1.0f, 0, smg, blockIdx.x, blockIdx.y);
}

// ---------------------------------------------------------------------------
// fp16 tensor-core flash attention (exp2 domain), occ-2, 3-stage — R14 config.
// ---------------------------------------------------------------------------
#define AQ 128
#define AK 64
#define NKT (S_ / AK)        // 32

#define SQ_  0
#define SK_(i) (16 * 1024 + (i) * 8 * 1024)      // K bufs at 16K,24K,32K
#define SV_(i) (40 * 1024 + (i) * 8 * 1024)      // V bufs at 40K,48K,56K
#define ASMEM (64 * 1024)

__global__ __launch_bounds__(256, 2)
void attn_mma_f16(const __half* __restrict__ Qg, const __half* __restrict__ Kg,
                  const __half* __restrict__ Vtg, __half* __restrict__ Ctx)
{
    extern __shared__ __align__(128) char sma[];
    const uint32_t sb = smem_u32(sma);
    const int tid = threadIdx.x;
    const int wid = tid >> 5;
    const int lane = tid & 31;
    const int qt = blockIdx.x;
    const int h  = blockIdx.y;
    const int b  = blockIdx.z;

    auto issue_q = [&]() {
#pragma unroll
        for (int i = 0; i < 4; ++i) {
            int idx = tid + 256 * i;
            int row = idx >> 3, c = idx & 7;
            uint32_t dst = sb + SQ_ + sw128((uint32_t)(row * 128 + c * 16));
            const __half* src = Qg + (size_t)((qt * AQ + row) * 2 + b) * E_ + h * DH_ + c * 8;
            CP_ASYNC16(dst, src);
        }
    };
    auto issue_kv = [&](int kt, int buf) {
        uint32_t kb = sb + SK_(buf);
        uint32_t vb = sb + SV_(buf);
#pragma unroll
        for (int i = 0; i < 2; ++i) {
            int idx = tid + 256 * i;
            int row = idx >> 3, c = idx & 7;
            uint32_t sw = sw128((uint32_t)(row * 128 + c * 16));
            const __half* ksrc = Kg + (size_t)((kt * AK + row) * 2 + b) * E_ + h * DH_ + c * 8;
            const __half* vsrc = Vtg + ((size_t)(b * H_ + h) * DH_ + row) * S_ + kt * AK + c * 8;
            CP_ASYNC16(kb + sw, ksrc);
            CP_ASYNC16(vb + sw, vsrc);
        }
    };

    issue_q();
    issue_kv(0, 0);
    CP_COMMIT();
    issue_kv(1, 1);
    CP_COMMIT();
    issue_kv(2, 2);
    CP_COMMIT();

    const int a_hi = (lane & 16) ? 1 : 0;
    const int b_row_rel = (lane & 7) + ((lane & 16) >> 1);
    const int b_hi = (lane & 8) ? 1 : 0;
    const int arow = wid * 16 + (lane & 15);

    float oc[8][4];
#pragma unroll
    for (int n = 0; n < 8; ++n)
#pragma unroll
        for (int r = 0; r < 4; ++r) oc[n][r] = 0.0f;
    float m0 = -1e30f, m1 = -1e30f, l0 = 0.0f, l1 = 0.0f;

    CP_WAIT2();
    __syncthreads();

    uint32_t qf[4][4];
#pragma unroll
    for (int s = 0; s < 4; ++s) {
        uint32_t off = (uint32_t)(arow * 128 + (2 * s + a_hi) * 16);
        ldsm_x4(sb + SQ_ + sw128(off), qf[s][0], qf[s][1], qf[s][2], qf[s][3]);
    }

    int buf = 0;
    for (int kt = 0; kt < NKT; ++kt) {
        const uint32_t kb = sb + SK_(buf);
        const uint32_t vb = sb + SV_(buf);

        float sc[8][4];
#pragma unroll
        for (int n = 0; n < 8; ++n)
#pragma unroll
            for (int r = 0; r < 4; ++r) sc[n][r] = 0.0f;

#pragma unroll
        for (int s = 0; s < 4; ++s) {
#pragma unroll
            for (int g = 0; g < 4; ++g) {
                int row = g * 16 + b_row_rel;
                uint32_t off = (uint32_t)(row * 128 + (2 * s + b_hi) * 16);
                uint32_t r0, r1, r2, r3;
                ldsm_x4(kb + sw128(off), r0, r1, r2, r3);
                uint32_t bf0[2] = { r0, r1 };
                uint32_t bf1[2] = { r2, r3 };
                mma_f16(sc[2 * g + 0], qf[s], bf0);
                mma_f16(sc[2 * g + 1], qf[s], bf1);
            }
        }

        {
            float mx0 = -1e30f, mx1 = -1e30f;
#pragma unroll
            for (int n = 0; n < 8; ++n) {
                mx0 = fmaxf(mx0, fmaxf(sc[n][0], sc[n][1]));
                mx1 = fmaxf(mx1, fmaxf(sc[n][2], sc[n][3]));
            }
            mx0 = fmaxf(mx0, __shfl_xor_sync(0xffffffffu, mx0, 1));
            mx0 = fmaxf(mx0, __shfl_xor_sync(0xffffffffu, mx0, 2));
            mx1 = fmaxf(mx1, __shfl_xor_sync(0xffffffffu, mx1, 1));
            mx1 = fmaxf(mx1, __shfl_xor_sync(0xffffffffu, mx1, 2));
            const float mn0 = fmaxf(m0, mx0);
            const float mn1 = fmaxf(m1, mx1);
            const float corr0 = exp2f(m0 - mn0);
            const float corr1 = exp2f(m1 - mn1);
            m0 = mn0; m1 = mn1;
            float rs0 = 0.0f, rs1 = 0.0f;
#pragma unroll
            for (int n = 0; n < 8; ++n) {
                oc[n][0] *= corr0; oc[n][1] *= corr0;
                oc[n][2] *= corr1; oc[n][3] *= corr1;
                sc[n][0] = exp2f(sc[n][0] - mn0);
                sc[n][1] = exp2f(sc[n][1] - mn0);
                sc[n][2] = exp2f(sc[n][2] - mn1);
                sc[n][3] = exp2f(sc[n][3] - mn1);
                rs0 += sc[n][0] + sc[n][1];
                rs1 += sc[n][2] + sc[n][3];
            }
            rs0 += __shfl_xor_sync(0xffffffffu, rs0, 1);
            rs0 += __shfl_xor_sync(0xffffffffu, rs0, 2);
            rs1 += __shfl_xor_sync(0xffffffffu, rs1, 1);
            rs1 += __shfl_xor_sync(0xffffffffu, rs1, 2);
            l0 = l0 * corr0 + rs0;
            l1 = l1 * corr1 + rs1;
        }

#pragma unroll
        for (int s = 0; s < 4; ++s) {
            uint32_t af[4];
            af[0] = pack_h2(sc[2 * s][0],     sc[2 * s][1]);
            af[1] = pack_h2(sc[2 * s][2],     sc[2 * s][3]);
            af[2] = pack_h2(sc[2 * s + 1][0], sc[2 * s + 1][1]);
            af[3] = pack_h2(sc[2 * s + 1][2], sc[2 * s + 1][3]);
#pragma unroll
            for (int g = 0; g < 4; ++g) {
                int row = g * 16 + b_row_rel;
                uint32_t off = (uint32_t)(row * 128 + (2 * s + b_hi) * 16);
                uint32_t r0, r1, r2, r3;
                ldsm_x4(vb + sw128(off), r0, r1, r2, r3);
                uint32_t bf0[2] = { r0, r1 };
                uint32_t bf1[2] = { r2, r3 };
                mma_f16(oc[2 * g + 0], af, bf0);
                mma_f16(oc[2 * g + 1], af, bf1);
            }
        }

        __syncthreads();
        if (kt + 3 < NKT) {
            issue_kv(kt + 3, buf);
        }
        CP_COMMIT();
        if (kt + 1 < NKT) {
            CP_WAIT2();
            __syncthreads();
        }
        buf = (buf == 2) ? 0 : buf + 1;
    }

    const int tg = lane & 3;
    const float inv0 = 1.0f / l0;
    const float inv1 = 1.0f / l1;
    const int q0 = qt * AQ + wid * 16 + (lane >> 2);
#pragma unroll
    for (int n = 0; n < 8; ++n) {
        const int col = h * DH_ + n * 8 + 2 * tg;
        uint32_t lo = pack_h2(oc[n][0] * inv0, oc[n][1] * inv0);
        uint32_t hi = pack_h2(oc[n][2] * inv1, oc[n][3] * inv1);
        *(uint32_t*)(Ctx + (size_t)(q0 * 2 + b) * E_ + col) = lo;
        *(uint32_t*)(Ctx + (size_t)((q0 + 8) * 2 + b) * E_ + col) = hi;
    }
}

// ---------------------------------------------------------------------------
// Launcher (4 launches)
// ---------------------------------------------------------------------------
extern "C" void kernel_launch(void* const* d_in, const int* in_sizes, int n_in,
                              void* d_out, int out_size)
{
    const float* query = (const float*)d_in[0];
    const float* wq = (const float*)d_in[1];
    const float* bq = (const float*)d_in[2];
    const float* wk = (const float*)d_in[3];
    const float* bk = (const float*)d_in[4];
    const float* wv = (const float*)d_in[5];
    const float* bv = (const float*)d_in[6];
    const float* wo = (const float*)d_in[7];
    const float* bo = (const float*)d_in[8];
    float* out = (float*)d_out;

    __half *hx, *hwq, *hwk, *hwv, *hwo, *qb, *kb, *vtb, *cb;
    cudaGetSymbolAddress((void**)&hx,  g_hx);
    cudaGetSymbolAddress((void**)&hwq, g_hwq);
    cudaGetSymbolAddress((void**)&hwk, g_hwk);
    cudaGetSymbolAddress((void**)&hwv, g_hwv);
    cudaGetSymbolAddress((void**)&hwo, g_hwo);
    cudaGetSymbolAddress((void**)&qb,  g_q);
    cudaGetSymbolAddress((void**)&kb,  g_k);
    cudaGetSymbolAddress((void**)&vtb, g_vt);
    cudaGetSymbolAddress((void**)&cb,  g_ctx);

    const int ntot4 = XN4 + 4 * WN4;
    cvt_all_f16<<<(ntot4 + 255) / 256, 256>>>(query, wq, wk, wv, wo,
                                              hx, hwq, hwk, hwv, hwo);

    cudaFuncSetAttribute(gemm_qkv_f16, cudaFuncAttributeMaxDynamicSharedMemorySize, GEMM_SMEM);
    cudaFuncSetAttribute(gemm_out_f16, cudaFuncAttributeMaxDynamicSharedMemorySize, GEMM_SMEM);
    cudaFuncSetAttribute(attn_mma_f16, cudaFuncAttributeMaxDynamicSharedMemorySize, ASMEM);

    gemm_qkv_f16<<<dim3(E_ / 128, M_ / 128, 3), 256, GEMM_SMEM>>>(
        hx, hwq, hwk, hwv, bq, bk, bv, qb, kb, vtb);

    attn_mma_f16<<<dim3(S_ / AQ, H_, B_), 256, ASMEM>>>(qb, kb, vtb, cb);

    gemm_out_f16<<<dim3(E_ / 128, M_ / 128), 256, GEMM_SMEM>>>(cb, hwo, bo, out);
}

// round 16
// speedup vs baseline: 1.0181x; 1.0181x over previous
#include <cuda_runtime.h>
#include <cuda_fp16.h>
#include <cstdint>

// Problem dims (fixed by the reference)
#define S_ 2048
#define B_ 2
#define E_ 1024
#define H_ 16
#define DH_ 64
#define M_ (S_ * B_)
#define SCALING_ 0.125f
#define LOG2E_ 1.4426950408889634f

// ---------------------------------------------------------------------------
// Scratch (allocation-free rule: __device__ globals), all fp16
// ---------------------------------------------------------------------------
__device__ __half g_hx[(size_t)M_ * E_];
__device__ __half g_hwq[(size_t)E_ * E_];
__device__ __half g_hwk[(size_t)E_ * E_];
__device__ __half g_hwv[(size_t)E_ * E_];
__device__ __half g_hwo[(size_t)E_ * E_];
__device__ __half g_q[(size_t)M_ * E_];      // (scaling*log2e)-prescaled Q
__device__ __half g_k[(size_t)M_ * E_];
__device__ __half g_vt[(size_t)M_ * E_];     // V transposed: [b][h][d][s]
__device__ __half g_ctx[(size_t)M_ * E_];

// ---------------------------------------------------------------------------
// Helpers (.target sm_103 safe)
// ---------------------------------------------------------------------------
__device__ __forceinline__ uint32_t smem_u32(const void* p) {
    uint32_t a;
    asm("{ .reg .u64 t; cvta.to.shared.u64 t, %1; cvt.u32.u64 %0, t; }"
        : "=r"(a) : "l"(p));
    return a;
}

__device__ __forceinline__ uint32_t pack_h2(float a, float b) {
    __half2 h = __floats2half2_rn(a, b);
    return *reinterpret_cast<uint32_t*>(&h);
}

__device__ __forceinline__ void ldsm_x4(uint32_t addr, uint32_t& r0, uint32_t& r1,
                                        uint32_t& r2, uint32_t& r3) {
    asm volatile("ldmatrix.sync.aligned.m8n8.x4.shared.b16 {%0,%1,%2,%3}, [%4];"
                 : "=r"(r0), "=r"(r1), "=r"(r2), "=r"(r3) : "r"(addr));
}

__device__ __forceinline__ void mma_f16(float* d, const uint32_t* a, const uint32_t* b) {
    asm volatile(
        "mma.sync.aligned.m16n8k16.row.col.f32.f16.f16.f32 "
        "{%0,%1,%2,%3}, {%4,%5,%6,%7}, {%8,%9}, {%0,%1,%2,%3};"
        : "+f"(d[0]), "+f"(d[1]), "+f"(d[2]), "+f"(d[3])
        : "r"(a[0]), "r"(a[1]), "r"(a[2]), "r"(a[3]), "r"(b[0]), "r"(b[1]));
}

#define CP_ASYNC16(dst, src) \
    asm volatile("cp.async.cg.shared.global [%0], [%1], 16;" \
                 :: "r"(dst), "l"(src) : "memory")
#define CP_COMMIT() asm volatile("cp.async.commit_group;" ::: "memory")
#define CP_WAIT1()  asm volatile("cp.async.wait_group 1;" ::: "memory")
#define CP_WAIT2()  asm volatile("cp.async.wait_group 2;" ::: "memory")
#define CP_WAIT0()  asm volatile("cp.async.wait_group 0;" ::: "memory")

__device__ __forceinline__ uint32_t sw128(uint32_t off) {
    return off ^ ((off >> 3) & 0x70);
}

// ---------------------------------------------------------------------------
// Batched fp32 -> fp16 convert
// ---------------------------------------------------------------------------
#define XN4 (M_ * E_ / 4)
#define WN4 (E_ * E_ / 4)

__global__ __launch_bounds__(256)
void cvt_all_f16(const float* __restrict__ x,
                 const float* __restrict__ w0, const float* __restrict__ w1,
                 const float* __restrict__ w2, const float* __restrict__ w3,
                 __half* __restrict__ hx,
                 __half* __restrict__ h0, __half* __restrict__ h1,
                 __half* __restrict__ h2, __half* __restrict__ h3)
{
    int i = blockIdx.x * blockDim.x + threadIdx.x;
    const float* src;
    __half* dst;
    int j;
    if (i < XN4)                { src = x;  dst = hx; j = i; }
    else if (i < XN4 + WN4)     { src = w0; dst = h0; j = i - XN4; }
    else if (i < XN4 + 2 * WN4) { src = w1; dst = h1; j = i - XN4 - WN4; }
    else if (i < XN4 + 3 * WN4) { src = w2; dst = h2; j = i - XN4 - 2 * WN4; }
    else                        { src = w3; dst = h3; j = i - XN4 - 3 * WN4; }
    float4 v = ((const float4*)src)[j];
    uint2 o;
    o.x = pack_h2(v.x, v.y);
    o.y = pack_h2(v.z, v.w);
    ((uint2*)dst)[j] = o;
}

// ---------------------------------------------------------------------------
// fp16 mma GEMM (NT) — R7/R10 config (fp32 accum, 8 warps, 64x32 warp tiles).
// CTA 128x128, BK=64 halfs, cp.async double buffer, occ 2.
// mode 0: fp32 out; 1: half out; 2: half transposed out [b][h][d][s].
// ---------------------------------------------------------------------------
#define GK 1024
#define BKH 64
#define NCH (GK / BKH)            // 16
#define OPB (128 * 128)           // 16 KB per operand per buffer
#define GEMM_SMEM 69632

__device__ __forceinline__
void gemm_body(const __half* __restrict__ A, const __half* __restrict__ W,
               const float* __restrict__ bias, void* __restrict__ Cout,
               float alpha, int mode, char* smg, int bx, int by)
{
    const uint32_t sb = smem_u32(smg);
    const uint32_t aB[2] = { sb, sb + 2 * OPB };
    const uint32_t bB[2] = { sb + OPB, sb + 3 * OPB };

    const int tid = threadIdx.x;          // 256 threads
    const int wid = tid >> 5;             // 0..7
    const int lane = tid & 31;
    const int warp_m = wid & 1;           // *64
    const int warp_n = wid >> 1;          // *32

    const __half* Ap = A + (size_t)(by * 128) * GK;
    const __half* Wp = W + (size_t)(bx * 128) * GK;

    const int ldrow = tid >> 3;
    const int ldc16 = tid & 7;

    const int a_hi = (lane & 16) ? 1 : 0;
    const int b_row_rel = (lane & 7) + ((lane & 16) >> 1);
    const int b_hi = (lane & 8) ? 1 : 0;

    float acc[4][4][4];
#pragma unroll
    for (int i = 0; i < 4; ++i)
#pragma unroll
        for (int j = 0; j < 4; ++j)
#pragma unroll
            for (int r = 0; r < 4; ++r) acc[i][j][r] = 0.0f;

    auto issue = [&](int c, int buf) {
#pragma unroll
        for (int i = 0; i < 4; ++i) {
            int row = ldrow + i * 32;
            uint32_t sw = sw128((uint32_t)(row * 128 + ldc16 * 16));
            const __half* ga = Ap + (size_t)row * GK + c * BKH + ldc16 * 8;
            const __half* gw = Wp + (size_t)row * GK + c * BKH + ldc16 * 8;
            CP_ASYNC16(aB[buf] + sw, ga);
            CP_ASYNC16(bB[buf] + sw, gw);
        }
    };

    issue(0, 0); CP_COMMIT();
    issue(1, 1); CP_COMMIT();

    for (int c = 0; c < NCH; ++c) {
        const int buf = c & 1;
        CP_WAIT1();
        __syncthreads();

#pragma unroll
        for (int s = 0; s < 4; ++s) {
            uint32_t bfr[4][2];
#pragma unroll
            for (int nfp = 0; nfp < 2; ++nfp) {
                int row = warp_n * 32 + nfp * 16 + b_row_rel;
                uint32_t off = (uint32_t)(row * 128 + (2 * s + b_hi) * 16);
                uint32_t r0, r1, r2, r3;
                ldsm_x4(bB[buf] + sw128(off), r0, r1, r2, r3);
                bfr[2 * nfp + 0][0] = r0; bfr[2 * nfp + 0][1] = r1;
                bfr[2 * nfp + 1][0] = r2; bfr[2 * nfp + 1][1] = r3;
            }
#pragma unroll
            for (int mf = 0; mf < 4; ++mf) {
                int row = warp_m * 64 + mf * 16 + (lane & 15);
                uint32_t off = (uint32_t)(row * 128 + (2 * s + a_hi) * 16);
                uint32_t af[4];
                ldsm_x4(aB[buf] + sw128(off), af[0], af[1], af[2], af[3]);
#pragma unroll
                for (int nf = 0; nf < 4; ++nf)
                    mma_f16(acc[mf][nf], af, bfr[nf]);
            }
        }
        __syncthreads();
        if (c + 2 < NCH) issue(c + 2, buf);
        CP_COMMIT();
    }

    const int gq = lane >> 2;
    const int tg = lane & 3;

    if (mode == 0) {
        float* C = (float*)Cout;
#pragma unroll
        for (int nf = 0; nf < 4; ++nf) {
            const int col = bx * 128 + warp_n * 32 + nf * 8 + 2 * tg;
            const float bv0 = bias[col], bv1 = bias[col + 1];
#pragma unroll
            for (int mf = 0; mf < 4; ++mf) {
                const int r0 = by * 128 + warp_m * 64 + mf * 16 + gq;
                float2 lo, hi;
                lo.x = alpha * (acc[mf][nf][0] + bv0);
                lo.y = alpha * (acc[mf][nf][1] + bv1);
                hi.x = alpha * (acc[mf][nf][2] + bv0);
                hi.y = alpha * (acc[mf][nf][3] + bv1);
                *(float2*)(C + (size_t)r0 * E_ + col) = lo;
                *(float2*)(C + (size_t)(r0 + 8) * E_ + col) = hi;
            }
        }
        return;
    }
    if (mode == 1) {
        __half* C = (__half*)Cout;
#pragma unroll
        for (int nf = 0; nf < 4; ++nf) {
            const int col = bx * 128 + warp_n * 32 + nf * 8 + 2 * tg;
            const float bv0 = bias[col], bv1 = bias[col + 1];
#pragma unroll
            for (int mf = 0; mf < 4; ++mf) {
                const int r0 = by * 128 + warp_m * 64 + mf * 16 + gq;
                uint32_t lo = pack_h2(alpha * (acc[mf][nf][0] + bv0),
                                      alpha * (acc[mf][nf][1] + bv1));
                uint32_t hi = pack_h2(alpha * (acc[mf][nf][2] + bv0),
                                      alpha * (acc[mf][nf][3] + bv1));
                *(uint32_t*)(C + (size_t)r0 * E_ + col) = lo;
                *(uint32_t*)(C + (size_t)(r0 + 8) * E_ + col) = hi;
            }
        }
        return;
    }

    // mode 2: transposed epilogue -> Cvt[b][h][d][s] as half
    CP_WAIT0();
    __syncthreads();
    float* Cs = (float*)smg;     // [128][132]
#pragma unroll
    for (int nf = 0; nf < 4; ++nf) {
        const int colL = warp_n * 32 + nf * 8 + 2 * tg;
        const int colG = bx * 128 + colL;
        const float bv0 = bias[colG], bv1 = bias[colG + 1];
#pragma unroll
        for (int mf = 0; mf < 4; ++mf) {
            const int r0 = warp_m * 64 + mf * 16 + gq;
            Cs[r0 * 132 + colL]           = acc[mf][nf][0] + bv0;
            Cs[r0 * 132 + colL + 1]       = acc[mf][nf][1] + bv1;
            Cs[(r0 + 8) * 132 + colL]     = acc[mf][nf][2] + bv0;
            Cs[(r0 + 8) * 132 + colL + 1] = acc[mf][nf][3] + bv1;
        }
    }
    __syncthreads();
    {
        __half* C = (__half*)Cout;
        const int col = tid >> 1;
        const int b = tid & 1;
        const int h = bx * 2 + (col >> 6);
        const int d = col & 63;
        __half* dst = C + ((size_t)(b * H_ + h) * DH_ + d) * S_ + by * 64;
#pragma unroll
        for (int j = 0; j < 16; ++j) {
            uint2 o;
            o.x = pack_h2(Cs[((4 * j + 0) * 2 + b) * 132 + col],
                          Cs[((4 * j + 1) * 2 + b) * 132 + col]);
            o.y = pack_h2(Cs[((4 * j + 2) * 2 + b) * 132 + col],
                          Cs[((4 * j + 3) * 2 + b) * 132 + col]);
            *(uint2*)(dst + 4 * j) = o;
        }
    }
}

// fused QKV: z = 0 -> Q (alpha = SCALING*LOG2E, half out), 1 -> K, 2 -> Vt
__global__ __launch_bounds__(256, 2)
void gemm_qkv_f16(const __half* __restrict__ A,
                  const __half* __restrict__ Wq, const __half* __restrict__ Wk,
                  const __half* __restrict__ Wv,
                  const float* __restrict__ bq, const float* __restrict__ bk,
                  const float* __restrict__ bv,
                  __half* __restrict__ Q, __half* __restrict__ K,
                  __half* __restrict__ Vt)
{
    extern __shared__ __align__(128) char smg[];
    const int z = blockIdx.z;
    const __half* W = (z == 0) ? Wq : (z == 1) ? Wk : Wv;
    const float* bias = (z == 0) ? bq : (z == 1) ? bk : bv;
    void* C = (z == 0) ? (void*)Q : (z == 1) ? (void*)K : (void*)Vt;
    const float alpha = (z == 0) ? SCALING_ * LOG2E_ : 1.0f;
    const int mode = (z == 2) ? 2 : 1;
    gemm_body(A, W, bias, C, alpha, mode, smg, blockIdx.x, blockIdx.y);
}

__global__ __launch_bounds__(256, 2)
void gemm_out_f16(const __half* __restrict__ A, const __half* __restrict__ W,
                  const float* __restrict__ bias, float* __restrict__ C)
{
    extern __shared__ __align__(128) char smg[];
    gemm_body(A, W, bias, C, 1.0f, 0, smg, blockIdx.x, blockIdx.y);
}

// ---------------------------------------------------------------------------
// fp16 tensor-core flash attention (exp2 domain), occ-2, 3-stage K/V pipeline.
// CTA = (q-tile 128, head, batch); 8 warps x 16 q-rows; K-tiles of 64.
// smem 64 KB -> still 2 CTAs/SM. Q fragments hoisted; P stays in registers.
// ---------------------------------------------------------------------------
#define AQ 128
#define AK 64
#define NKT (S_ / AK)        // 32

#define SQ_  0
#define SK_(i) (16 * 1024 + (i) * 8 * 1024)      // K bufs at 16K,24K,32K
#define SV_(i) (40 * 1024 + (i) * 8 * 1024)      // V bufs at 40K,48K,56K
#define ASMEM (64 * 1024)

__global__ __launch_bounds__(256, 2)
void attn_mma_f16(const __half* __restrict__ Qg, const __half* __restrict__ Kg,
                  const __half* __restrict__ Vtg, __half* __restrict__ Ctx)
{
    extern __shared__ __align__(128) char sma[];
    const uint32_t sb = smem_u32(sma);
    const int tid = threadIdx.x;
    const int wid = tid >> 5;
    const int lane = tid & 31;
    const int qt = blockIdx.x;
    const int h  = blockIdx.y;
    const int b  = blockIdx.z;

    auto issue_q = [&]() {
#pragma unroll
        for (int i = 0; i < 4; ++i) {
            int idx = tid + 256 * i;
            int row = idx >> 3, c = idx & 7;
            uint32_t dst = sb + SQ_ + sw128((uint32_t)(row * 128 + c * 16));
            const __half* src = Qg + (size_t)((qt * AQ + row) * 2 + b) * E_ + h * DH_ + c * 8;
            CP_ASYNC16(dst, src);
        }
    };
    auto issue_kv = [&](int kt, int buf) {
        uint32_t kb = sb + SK_(buf);
        uint32_t vb = sb + SV_(buf);
#pragma unroll
        for (int i = 0; i < 2; ++i) {
            int idx = tid + 256 * i;
            int row = idx >> 3, c = idx & 7;
            uint32_t sw = sw128((uint32_t)(row * 128 + c * 16));
            const __half* ksrc = Kg + (size_t)((kt * AK + row) * 2 + b) * E_ + h * DH_ + c * 8;
            const __half* vsrc = Vtg + ((size_t)(b * H_ + h) * DH_ + row) * S_ + kt * AK + c * 8;
            CP_ASYNC16(kb + sw, ksrc);
            CP_ASYNC16(vb + sw, vsrc);
        }
    };

    // prologue: Q + first 3 K/V tiles (groups: {Q,kv0}, {kv1}, {kv2})
    issue_q();
    issue_kv(0, 0);
    CP_COMMIT();
    issue_kv(1, 1);
    CP_COMMIT();
    issue_kv(2, 2);
    CP_COMMIT();

    const int a_hi = (lane & 16) ? 1 : 0;
    const int b_row_rel = (lane & 7) + ((lane & 16) >> 1);
    const int b_hi = (lane & 8) ? 1 : 0;
    const int arow = wid * 16 + (lane & 15);

    float oc[8][4];
#pragma unroll
    for (int n = 0; n < 8; ++n)
#pragma unroll
        for (int r = 0; r < 4; ++r) oc[n][r] = 0.0f;
    float m0 = -1e30f, m1 = -1e30f, l0 = 0.0f, l1 = 0.0f;

    // wait for {Q, kv0} (2 groups may remain pending)
    CP_WAIT2();
    __syncthreads();

    // hoist Q fragments (read once, reused 32x)
    uint32_t qf[4][4];
#pragma unroll
    for (int s = 0; s < 4; ++s) {
        uint32_t off = (uint32_t)(arow * 128 + (2 * s + a_hi) * 16);
        ldsm_x4(sb + SQ_ + sw128(off), qf[s][0], qf[s][1], qf[s][2], qf[s][3]);
    }

    int buf = 0;
    for (int kt = 0; kt < NKT; ++kt) {
        const uint32_t kb = sb + SK_(buf);
        const uint32_t vb = sb + SV_(buf);

        // ---- S' = (scaled Q) K^T : 8 n-frags
        float sc[8][4];
#pragma unroll
        for (int n = 0; n < 8; ++n)
#pragma unroll
            for (int r = 0; r < 4; ++r) sc[n][r] = 0.0f;

#pragma unroll
        for (int s = 0; s < 4; ++s) {
#pragma unroll
            for (int g = 0; g < 4; ++g) {
                int row = g * 16 + b_row_rel;
                uint32_t off = (uint32_t)(row * 128 + (2 * s + b_hi) * 16);
                uint32_t r0, r1, r2, r3;
                ldsm_x4(kb + sw128(off), r0, r1, r2, r3);
                uint32_t bf0[2] = { r0, r1 };
                uint32_t bf1[2] = { r2, r3 };
                mma_f16(sc[2 * g + 0], qf[s], bf0);
                mma_f16(sc[2 * g + 1], qf[s], bf1);
            }
        }

        // ---- online softmax in exp2 domain
        {
            float mx0 = -1e30f, mx1 = -1e30f;
#pragma unroll
            for (int n = 0; n < 8; ++n) {
                mx0 = fmaxf(mx0, fmaxf(sc[n][0], sc[n][1]));
                mx1 = fmaxf(mx1, fmaxf(sc[n][2], sc[n][3]));
            }
            mx0 = fmaxf(mx0, __shfl_xor_sync(0xffffffffu, mx0, 1));
            mx0 = fmaxf(mx0, __shfl_xor_sync(0xffffffffu, mx0, 2));
            mx1 = fmaxf(mx1, __shfl_xor_sync(0xffffffffu, mx1, 1));
            mx1 = fmaxf(mx1, __shfl_xor_sync(0xffffffffu, mx1, 2));
            const float mn0 = fmaxf(m0, mx0);
            const float mn1 = fmaxf(m1, mx1);
            const float corr0 = exp2f(m0 - mn0);
            const float corr1 = exp2f(m1 - mn1);
            m0 = mn0; m1 = mn1;
            float rs0 = 0.0f, rs1 = 0.0f;
#pragma unroll
            for (int n = 0; n < 8; ++n) {
                oc[n][0] *= corr0; oc[n][1] *= corr0;
                oc[n][2] *= corr1; oc[n][3] *= corr1;
                sc[n][0] = exp2f(sc[n][0] - mn0);
                sc[n][1] = exp2f(sc[n][1] - mn0);
                sc[n][2] = exp2f(sc[n][2] - mn1);
                sc[n][3] = exp2f(sc[n][3] - mn1);
                rs0 += sc[n][0] + sc[n][1];
                rs1 += sc[n][2] + sc[n][3];
            }
            rs0 += __shfl_xor_sync(0xffffffffu, rs0, 1);
            rs0 += __shfl_xor_sync(0xffffffffu, rs0, 2);
            rs1 += __shfl_xor_sync(0xffffffffu, rs1, 1);
            rs1 += __shfl_xor_sync(0xffffffffu, rs1, 2);
            l0 = l0 * corr0 + rs0;
            l1 = l1 * corr1 + rs1;
        }

        // ---- O += P V (P packed from sc registers)
#pragma unroll
        for (int s = 0; s < 4; ++s) {
            uint32_t af[4];
            af[0] = pack_h2(sc[2 * s][0],     sc[2 * s][1]);
            af[1] = pack_h2(sc[2 * s][2],     sc[2 * s][3]);
            af[2] = pack_h2(sc[2 * s + 1][0], sc[2 * s + 1][1]);
            af[3] = pack_h2(sc[2 * s + 1][2], sc[2 * s + 1][3]);
#pragma unroll
            for (int g = 0; g < 4; ++g) {
                int row = g * 16 + b_row_rel;
                uint32_t off = (uint32_t)(row * 128 + (2 * s + b_hi) * 16);
                uint32_t r0, r1, r2, r3;
                ldsm_x4(vb + sw128(off), r0, r1, r2, r3);
                uint32_t bf0[2] = { r0, r1 };
                uint32_t bf1[2] = { r2, r3 };
                mma_f16(oc[2 * g + 0], af, bf0);
                mma_f16(oc[2 * g + 1], af, bf1);
            }
        }

        __syncthreads();                   // all warps done reading buf
        if (kt + 3 < NKT) {
            issue_kv(kt + 3, buf);         // refill the buffer just freed
        }
        CP_COMMIT();
        if (kt + 1 < NKT) {
            CP_WAIT2();                    // tile kt+1 landed (2 may pend)
            __syncthreads();
        }
        buf = (buf == 2) ? 0 : buf + 1;
    }

    // ---- epilogue: ctx half [(q*B+b)*E + h*64 + col]
    const int tg = lane & 3;
    const float inv0 = 1.0f / l0;
    const float inv1 = 1.0f / l1;
    const int q0 = qt * AQ + wid * 16 + (lane >> 2);
#pragma unroll
    for (int n = 0; n < 8; ++n) {
        const int col = h * DH_ + n * 8 + 2 * tg;
        uint32_t lo = pack_h2(oc[n][0] * inv0, oc[n][1] * inv0);
        uint32_t hi = pack_h2(oc[n][2] * inv1, oc[n][3] * inv1);
        *(uint32_t*)(Ctx + (size_t)(q0 * 2 + b) * E_ + col) = lo;
        *(uint32_t*)(Ctx + (size_t)((q0 + 8) * 2 + b) * E_ + col) = hi;
    }
}

// ---------------------------------------------------------------------------
// Launcher (4 launches)
// ---------------------------------------------------------------------------
extern "C" void kernel_launch(void* const* d_in, const int* in_sizes, int n_in,
                              void* d_out, int out_size)
{
    const float* query = (const float*)d_in[0];
    const float* wq = (const float*)d_in[1];
    const float* bq = (const float*)d_in[2];
    const float* wk = (const float*)d_in[3];
    const float* bk = (const float*)d_in[4];
    const float* wv = (const float*)d_in[5];
    const float* bv = (const float*)d_in[6];
    const float* wo = (const float*)d_in[7];
    const float* bo = (const float*)d_in[8];
    float* out = (float*)d_out;

    __half *hx, *hwq, *hwk, *hwv, *hwo, *qb, *kb, *vtb, *cb;
    cudaGetSymbolAddress((void**)&hx,  g_hx);
    cudaGetSymbolAddress((void**)&hwq, g_hwq);
    cudaGetSymbolAddress((void**)&hwk, g_hwk);
    cudaGetSymbolAddress((void**)&hwv, g_hwv);
    cudaGetSymbolAddress((void**)&hwo, g_hwo);
    cudaGetSymbolAddress((void**)&qb,  g_q);
    cudaGetSymbolAddress((void**)&kb,  g_k);
    cudaGetSymbolAddress((void**)&vtb, g_vt);
    cudaGetSymbolAddress((void**)&cb,  g_ctx);

    const int ntot4 = XN4 + 4 * WN4;
    cvt_all_f16<<<(ntot4 + 255) / 256, 256>>>(query, wq, wk, wv, wo,
                                              hx, hwq, hwk, hwv, hwo);

    cudaFuncSetAttribute(gemm_qkv_f16, cudaFuncAttributeMaxDynamicSharedMemorySize, GEMM_SMEM);
    cudaFuncSetAttribute(gemm_out_f16, cudaFuncAttributeMaxDynamicSharedMemorySize, GEMM_SMEM);
    cudaFuncSetAttribute(attn_mma_f16, cudaFuncAttributeMaxDynamicSharedMemorySize, ASMEM);

    gemm_qkv_f16<<<dim3(E_ / 128, M_ / 128, 3), 256, GEMM_SMEM>>>(
        hx, hwq, hwk, hwv, bq, bk, bv, qb, kb, vtb);

    attn_mma_f16<<<dim3(S_ / AQ, H_, B_), 256, ASMEM>>>(qb, kb, vtb, cb);

    gemm_out_f16<<<dim3(E_ / 128, M_ / 128), 256, GEMM_SMEM>>>(cb, hwo, bo, out);
}

// round 17
// speedup vs baseline: 1.0269x; 1.0086x over previous
#include <cuda_runtime.h>
#include <cuda_fp16.h>
#include <cstdint>

// Problem dims (fixed by the reference)
#define S_ 2048
#define B_ 2
#define E_ 1024
#define H_ 16
#define DH_ 64
#define M_ (S_ * B_)
#define SCALING_ 0.125f
#define LOG2E_ 1.4426950408889634f

// ---------------------------------------------------------------------------
// Scratch (allocation-free rule: __device__ globals), all fp16
// ---------------------------------------------------------------------------
__device__ __half g_hx[(size_t)M_ * E_];
__device__ __half g_hwq[(size_t)E_ * E_];
__device__ __half g_hwk[(size_t)E_ * E_];
__device__ __half g_hwv[(size_t)E_ * E_];
__device__ __half g_hwo[(size_t)E_ * E_];
__device__ __half g_q[(size_t)M_ * E_];      // (scaling*log2e)-prescaled Q
__device__ __half g_k[(size_t)M_ * E_];
__device__ __half g_vt[(size_t)M_ * E_];     // V transposed: [b][h][d][s]
__device__ __half g_ctx[(size_t)M_ * E_];

// ---------------------------------------------------------------------------
// Helpers (.target sm_103 safe)
// ---------------------------------------------------------------------------
__device__ __forceinline__ uint32_t smem_u32(const void* p) {
    uint32_t a;
    asm("{ .reg .u64 t; cvta.to.shared.u64 t, %1; cvt.u32.u64 %0, t; }"
        : "=r"(a) : "l"(p));
    return a;
}

__device__ __forceinline__ uint32_t pack_h2(float a, float b) {
    __half2 h = __floats2half2_rn(a, b);
    return *reinterpret_cast<uint32_t*>(&h);
}

__device__ __forceinline__ void ldsm_x4(uint32_t addr, uint32_t& r0, uint32_t& r1,
                                        uint32_t& r2, uint32_t& r3) {
    asm volatile("ldmatrix.sync.aligned.m8n8.x4.shared.b16 {%0,%1,%2,%3}, [%4];"
                 : "=r"(r0), "=r"(r1), "=r"(r2), "=r"(r3) : "r"(addr));
}

__device__ __forceinline__ void mma_f16(float* d, const uint32_t* a, const uint32_t* b) {
    asm volatile(
        "mma.sync.aligned.m16n8k16.row.col.f32.f16.f16.f32 "
        "{%0,%1,%2,%3}, {%4,%5,%6,%7}, {%8,%9}, {%0,%1,%2,%3};"
        : "+f"(d[0]), "+f"(d[1]), "+f"(d[2]), "+f"(d[3])
        : "r"(a[0]), "r"(a[1]), "r"(a[2]), "r"(a[3]), "r"(b[0]), "r"(b[1]));
}

#define CP_ASYNC16(dst, src) \
    asm volatile("cp.async.cg.shared.global [%0], [%1], 16;" \
                 :: "r"(dst), "l"(src) : "memory")
#define CP_COMMIT() asm volatile("cp.async.commit_group;" ::: "memory")
#define CP_WAIT1()  asm volatile("cp.async.wait_group 1;" ::: "memory")
#define CP_WAIT2()  asm volatile("cp.async.wait_group 2;" ::: "memory")
#define CP_WAIT0()  asm volatile("cp.async.wait_group 0;" ::: "memory")

__device__ __forceinline__ uint32_t sw128(uint32_t off) {
    return off ^ ((off >> 3) & 0x70);
}

// ---------------------------------------------------------------------------
// Batched fp32 -> fp16 convert: 4 float4 per thread, block-uniform source.
// Block covers 1024 consecutive float4. Segment boundaries (XN4=1024 blocks,
// WN4=256 blocks each) align to block granularity -> uniform branch.
// ---------------------------------------------------------------------------
#define XN4 (M_ * E_ / 4)        // 1048576 -> 1024 blocks
#define WN4 (E_ * E_ / 4)        // 262144  -> 256 blocks
#define CVT_BLOCKS (1024 + 4 * 256)   // 2048

__global__ __launch_bounds__(256)
void cvt_all_f16(const float* __restrict__ x,
                 const float* __restrict__ w0, const float* __restrict__ w1,
                 const float* __restrict__ w2, const float* __restrict__ w3,
                 __half* __restrict__ hx,
                 __half* __restrict__ h0, __half* __restrict__ h1,
                 __half* __restrict__ h2, __half* __restrict__ h3)
{
    const int blk = blockIdx.x;
    const float* src;
    __half* dst;
    int base;                      // float4 index of this block's start
    if (blk < 1024)       { src = x;  dst = hx; base = blk * 1024; }
    else if (blk < 1280)  { src = w0; dst = h0; base = (blk - 1024) * 1024; }
    else if (blk < 1536)  { src = w1; dst = h1; base = (blk - 1280) * 1024; }
    else if (blk < 1792)  { src = w2; dst = h2; base = (blk - 1536) * 1024; }
    else                  { src = w3; dst = h3; base = (blk - 1792) * 1024; }

    const int t = base + threadIdx.x;
    float4 v0 = ((const float4*)src)[t];
    float4 v1 = ((const float4*)src)[t + 256];
    float4 v2 = ((const float4*)src)[t + 512];
    float4 v3 = ((const float4*)src)[t + 768];
    uint2 o0, o1, o2, o3;
    o0.x = pack_h2(v0.x, v0.y); o0.y = pack_h2(v0.z, v0.w);
    o1.x = pack_h2(v1.x, v1.y); o1.y = pack_h2(v1.z, v1.w);
    o2.x = pack_h2(v2.x, v2.y); o2.y = pack_h2(v2.z, v2.w);
    o3.x = pack_h2(v3.x, v3.y); o3.y = pack_h2(v3.z, v3.w);
    ((uint2*)dst)[t]       = o0;
    ((uint2*)dst)[t + 256] = o1;
    ((uint2*)dst)[t + 512] = o2;
    ((uint2*)dst)[t + 768] = o3;
}

// ---------------------------------------------------------------------------
// fp16 mma GEMM (NT) — R7/R10 config (fp32 accum, 8 warps, 64x32 warp tiles).
// CTA 128x128, BK=64 halfs, cp.async double buffer, occ 2.
// mode 0: fp32 out; 1: half out; 2: half transposed out [b][h][d][s].
// ---------------------------------------------------------------------------
#define GK 1024
#define BKH 64
#define NCH (GK / BKH)            // 16
#define OPB (128 * 128)           // 16 KB per operand per buffer
#define GEMM_SMEM 69632

__device__ __forceinline__
void gemm_body(const __half* __restrict__ A, const __half* __restrict__ W,
               const float* __restrict__ bias, void* __restrict__ Cout,
               float alpha, int mode, char* smg, int bx, int by)
{
    const uint32_t sb = smem_u32(smg);
    const uint32_t aB[2] = { sb, sb + 2 * OPB };
    const uint32_t bB[2] = { sb + OPB, sb + 3 * OPB };

    const int tid = threadIdx.x;          // 256 threads
    const int wid = tid >> 5;             // 0..7
    const int lane = tid & 31;
    const int warp_m = wid & 1;           // *64
    const int warp_n = wid >> 1;          // *32

    const __half* Ap = A + (size_t)(by * 128) * GK;
    const __half* Wp = W + (size_t)(bx * 128) * GK;

    const int ldrow = tid >> 3;
    const int ldc16 = tid & 7;

    const int a_hi = (lane & 16) ? 1 : 0;
    const int b_row_rel = (lane & 7) + ((lane & 16) >> 1);
    const int b_hi = (lane & 8) ? 1 : 0;

    float acc[4][4][4];
#pragma unroll
    for (int i = 0; i < 4; ++i)
#pragma unroll
        for (int j = 0; j < 4; ++j)
#pragma unroll
            for (int r = 0; r < 4; ++r) acc[i][j][r] = 0.0f;

    auto issue = [&](int c, int buf) {
#pragma unroll
        for (int i = 0; i < 4; ++i) {
            int row = ldrow + i * 32;
            uint32_t sw = sw128((uint32_t)(row * 128 + ldc16 * 16));
            const __half* ga = Ap + (size_t)row * GK + c * BKH + ldc16 * 8;
            const __half* gw = Wp + (size_t)row * GK + c * BKH + ldc16 * 8;
            CP_ASYNC16(aB[buf] + sw, ga);
            CP_ASYNC16(bB[buf] + sw, gw);
        }
    };

    issue(0, 0); CP_COMMIT();
    issue(1, 1); CP_COMMIT();

    for (int c = 0; c < NCH; ++c) {
        const int buf = c & 1;
        CP_WAIT1();
        __syncthreads();

#pragma unroll
        for (int s = 0; s < 4; ++s) {
            uint32_t bfr[4][2];
#pragma unroll
            for (int nfp = 0; nfp < 2; ++nfp) {
                int row = warp_n * 32 + nfp * 16 + b_row_rel;
                uint32_t off = (uint32_t)(row * 128 + (2 * s + b_hi) * 16);
                uint32_t r0, r1, r2, r3;
                ldsm_x4(bB[buf] + sw128(off), r0, r1, r2, r3);
                bfr[2 * nfp + 0][0] = r0; bfr[2 * nfp + 0][1] = r1;
                bfr[2 * nfp + 1][0] = r2; bfr[2 * nfp + 1][1] = r3;
            }
#pragma unroll
            for (int mf = 0; mf < 4; ++mf) {
                int row = warp_m * 64 + mf * 16 + (lane & 15);
                uint32_t off = (uint32_t)(row * 128 + (2 * s + a_hi) * 16);
                uint32_t af[4];
                ldsm_x4(aB[buf] + sw128(off), af[0], af[1], af[2], af[3]);
#pragma unroll
                for (int nf = 0; nf < 4; ++nf)
                    mma_f16(acc[mf][nf], af, bfr[nf]);
            }
        }
        __syncthreads();
        if (c + 2 < NCH) issue(c + 2, buf);
        CP_COMMIT();
    }

    const int gq = lane >> 2;
    const int tg = lane & 3;

    if (mode == 0) {
        float* C = (float*)Cout;
#pragma unroll
        for (int nf = 0; nf < 4; ++nf) {
            const int col = bx * 128 + warp_n * 32 + nf * 8 + 2 * tg;
            const float bv0 = bias[col], bv1 = bias[col + 1];
#pragma unroll
            for (int mf = 0; mf < 4; ++mf) {
                const int r0 = by * 128 + warp_m * 64 + mf * 16 + gq;
                float2 lo, hi;
                lo.x = alpha * (acc[mf][nf][0] + bv0);
                lo.y = alpha * (acc[mf][nf][1] + bv1);
                hi.x = alpha * (acc[mf][nf][2] + bv0);
                hi.y = alpha * (acc[mf][nf][3] + bv1);
                *(float2*)(C + (size_t)r0 * E_ + col) = lo;
                *(float2*)(C + (size_t)(r0 + 8) * E_ + col) = hi;
            }
        }
        return;
    }
    if (mode == 1) {
        __half* C = (__half*)Cout;
#pragma unroll
        for (int nf = 0; nf < 4; ++nf) {
            const int col = bx * 128 + warp_n * 32 + nf * 8 + 2 * tg;
            const float bv0 = bias[col], bv1 = bias[col + 1];
#pragma unroll
            for (int mf = 0; mf < 4; ++mf) {
                const int r0 = by * 128 + warp_m * 64 + mf * 16 + gq;
                uint32_t lo = pack_h2(alpha * (acc[mf][nf][0] + bv0),
                                      alpha * (acc[mf][nf][1] + bv1));
                uint32_t hi = pack_h2(alpha * (acc[mf][nf][2] + bv0),
                                      alpha * (acc[mf][nf][3] + bv1));
                *(uint32_t*)(C + (size_t)r0 * E_ + col) = lo;
                *(uint32_t*)(C + (size_t)(r0 + 8) * E_ + col) = hi;
            }
        }
        return;
    }

    // mode 2: transposed epilogue -> Cvt[b][h][d][s] as half
    CP_WAIT0();
    __syncthreads();
    float* Cs = (float*)smg;     // [128][132]
#pragma unroll
    for (int nf = 0; nf < 4; ++nf) {
        const int colL = warp_n * 32 + nf * 8 + 2 * tg;
        const int colG = bx * 128 + colL;
        const float bv0 = bias[colG], bv1 = bias[colG + 1];
#pragma unroll
        for (int mf = 0; mf < 4; ++mf) {
            const int r0 = warp_m * 64 + mf * 16 + gq;
            Cs[r0 * 132 + colL]           = acc[mf][nf][0] + bv0;
            Cs[r0 * 132 + colL + 1]       = acc[mf][nf][1] + bv1;
            Cs[(r0 + 8) * 132 + colL]     = acc[mf][nf][2] + bv0;
            Cs[(r0 + 8) * 132 + colL + 1] = acc[mf][nf][3] + bv1;
        }
    }
    __syncthreads();
    {
        __half* C = (__half*)Cout;
        const int col = tid >> 1;
        const int b = tid & 1;
        const int h = bx * 2 + (col >> 6);
        const int d = col & 63;
        __half* dst = C + ((size_t)(b * H_ + h) * DH_ + d) * S_ + by * 64;
#pragma unroll
        for (int j = 0; j < 16; ++j) {
            uint2 o;
            o.x = pack_h2(Cs[((4 * j + 0) * 2 + b) * 132 + col],
                          Cs[((4 * j + 1) * 2 + b) * 132 + col]);
            o.y = pack_h2(Cs[((4 * j + 2) * 2 + b) * 132 + col],
                          Cs[((4 * j + 3) * 2 + b) * 132 + col]);
            *(uint2*)(dst + 4 * j) = o;
        }
    }
}

// fused QKV: z = 0 -> Q (alpha = SCALING*LOG2E, half out), 1 -> K, 2 -> Vt
__global__ __launch_bounds__(256, 2)
void gemm_qkv_f16(const __half* __restrict__ A,
                  const __half* __restrict__ Wq, const __half* __restrict__ Wk,
                  const __half* __restrict__ Wv,
                  const float* __restrict__ bq, const float* __restrict__ bk,
                  const float* __restrict__ bv,
                  __half* __restrict__ Q, __half* __restrict__ K,
                  __half* __restrict__ Vt)
{
    extern __shared__ __align__(128) char smg[];
    const int z = blockIdx.z;
    const __half* W = (z == 0) ? Wq : (z == 1) ? Wk : Wv;
    const float* bias = (z == 0) ? bq : (z == 1) ? bk : bv;
    void* C = (z == 0) ? (void*)Q : (z == 1) ? (void*)K : (void*)Vt;
    const float alpha = (z == 0) ? SCALING_ * LOG2E_ : 1.0f;
    const int mode = (z == 2) ? 2 : 1;
    gemm_body(A, W, bias, C, alpha, mode, smg, blockIdx.x, blockIdx.y);
}

__global__ __launch_bounds__(256, 2)
void gemm_out_f16(const __half* __restrict__ A, const __half* __restrict__ W,
                  const float* __restrict__ bias, float* __restrict__ C)
{
    extern __shared__ __align__(128) char smg[];
    gemm_body(A, W, bias, C, 1.0f, 0, smg, blockIdx.x, blockIdx.y);
}

// ---------------------------------------------------------------------------
// fp16 tensor-core flash attention (exp2 domain), occ-2, 3-stage K/V pipeline.
// CTA = (q-tile 128, head, batch); 8 warps x 16 q-rows; K-tiles of 64.
// smem 64 KB -> still 2 CTAs/SM. Q fragments hoisted; P stays in registers.
// ---------------------------------------------------------------------------
#define AQ 128
#define AK 64
#define NKT (S_ / AK)        // 32

#define SQ_  0
#define SK_(i) (16 * 1024 + (i) * 8 * 1024)      // K bufs at 16K,24K,32K
#define SV_(i) (40 * 1024 + (i) * 8 * 1024)      // V bufs at 40K,48K,56K
#define ASMEM (64 * 1024)

__global__ __launch_bounds__(256, 2)
void attn_mma_f16(const __half* __restrict__ Qg, const __half* __restrict__ Kg,
                  const __half* __restrict__ Vtg, __half* __restrict__ Ctx)
{
    extern __shared__ __align__(128) char sma[];
    const uint32_t sb = smem_u32(sma);
    const int tid = threadIdx.x;
    const int wid = tid >> 5;
    const int lane = tid & 31;
    const int qt = blockIdx.x;
    const int h  = blockIdx.y;
    const int b  = blockIdx.z;

    auto issue_q = [&]() {
#pragma unroll
        for (int i = 0; i < 4; ++i) {
            int idx = tid + 256 * i;
            int row = idx >> 3, c = idx & 7;
            uint32_t dst = sb + SQ_ + sw128((uint32_t)(row * 128 + c * 16));
            const __half* src = Qg + (size_t)((qt * AQ + row) * 2 + b) * E_ + h * DH_ + c * 8;
            CP_ASYNC16(dst, src);
        }
    };
    auto issue_kv = [&](int kt, int buf) {
        uint32_t kb = sb + SK_(buf);
        uint32_t vb = sb + SV_(buf);
#pragma unroll
        for (int i = 0; i < 2; ++i) {
            int idx = tid + 256 * i;
            int row = idx >> 3, c = idx & 7;
            uint32_t sw = sw128((uint32_t)(row * 128 + c * 16));
            const __half* ksrc = Kg + (size_t)((kt * AK + row) * 2 + b) * E_ + h * DH_ + c * 8;
            const __half* vsrc = Vtg + ((size_t)(b * H_ + h) * DH_ + row) * S_ + kt * AK + c * 8;
            CP_ASYNC16(kb + sw, ksrc);
            CP_ASYNC16(vb + sw, vsrc);
        }
    };

    // prologue: Q + first 3 K/V tiles (groups: {Q,kv0}, {kv1}, {kv2})
    issue_q();
    issue_kv(0, 0);
    CP_COMMIT();
    issue_kv(1, 1);
    CP_COMMIT();
    issue_kv(2, 2);
    CP_COMMIT();

    const int a_hi = (lane & 16) ? 1 : 0;
    const int b_row_rel = (lane & 7) + ((lane & 16) >> 1);
    const int b_hi = (lane & 8) ? 1 : 0;
    const int arow = wid * 16 + (lane & 15);

    float oc[8][4];
#pragma unroll
    for (int n = 0; n < 8; ++n)
#pragma unroll
        for (int r = 0; r < 4; ++r) oc[n][r] = 0.0f;
    float m0 = -1e30f, m1 = -1e30f, l0 = 0.0f, l1 = 0.0f;

    // wait for {Q, kv0} (2 groups may remain pending)
    CP_WAIT2();
    __syncthreads();

    // hoist Q fragments (read once, reused 32x)
    uint32_t qf[4][4];
#pragma unroll
    for (int s = 0; s < 4; ++s) {
        uint32_t off = (uint32_t)(arow * 128 + (2 * s + a_hi) * 16);
        ldsm_x4(sb + SQ_ + sw128(off), qf[s][0], qf[s][1], qf[s][2], qf[s][3]);
    }

    int buf = 0;
    for (int kt = 0; kt < NKT; ++kt) {
        const uint32_t kb = sb + SK_(buf);
        const uint32_t vb = sb + SV_(buf);

        // ---- S' = (scaled Q) K^T : 8 n-frags
        float sc[8][4];
#pragma unroll
        for (int n = 0; n < 8; ++n)
#pragma unroll
            for (int r = 0; r < 4; ++r) sc[n][r] = 0.0f;

#pragma unroll
        for (int s = 0; s < 4; ++s) {
#pragma unroll
            for (int g = 0; g < 4; ++g) {
                int row = g * 16 + b_row_rel;
                uint32_t off = (uint32_t)(row * 128 + (2 * s + b_hi) * 16);
                uint32_t r0, r1, r2, r3;
                ldsm_x4(kb + sw128(off), r0, r1, r2, r3);
                uint32_t bf0[2] = { r0, r1 };
                uint32_t bf1[2] = { r2, r3 };
                mma_f16(sc[2 * g + 0], qf[s], bf0);
                mma_f16(sc[2 * g + 1], qf[s], bf1);
            }
        }

        // ---- online softmax in exp2 domain
        {
            float mx0 = -1e30f, mx1 = -1e30f;
#pragma unroll
            for (int n = 0; n < 8; ++n) {
                mx0 = fmaxf(mx0, fmaxf(sc[n][0], sc[n][1]));
                mx1 = fmaxf(mx1, fmaxf(sc[n][2], sc[n][3]));
            }
            mx0 = fmaxf(mx0, __shfl_xor_sync(0xffffffffu, mx0, 1));
            mx0 = fmaxf(mx0, __shfl_xor_sync(0xffffffffu, mx0, 2));
            mx1 = fmaxf(mx1, __shfl_xor_sync(0xffffffffu, mx1, 1));
            mx1 = fmaxf(mx1, __shfl_xor_sync(0xffffffffu, mx1, 2));
            const float mn0 = fmaxf(m0, mx0);
            const float mn1 = fmaxf(m1, mx1);
            const float corr0 = exp2f(m0 - mn0);
            const float corr1 = exp2f(m1 - mn1);
            m0 = mn0; m1 = mn1;
            float rs0 = 0.0f, rs1 = 0.0f;
#pragma unroll
            for (int n = 0; n < 8; ++n) {
                oc[n][0] *= corr0; oc[n][1] *= corr0;
                oc[n][2] *= corr1; oc[n][3] *= corr1;
                sc[n][0] = exp2f(sc[n][0] - mn0);
                sc[n][1] = exp2f(sc[n][1] - mn0);
                sc[n][2] = exp2f(sc[n][2] - mn1);
                sc[n][3] = exp2f(sc[n][3] - mn1);
                rs0 += sc[n][0] + sc[n][1];
                rs1 += sc[n][2] + sc[n][3];
            }
            rs0 += __shfl_xor_sync(0xffffffffu, rs0, 1);
            rs0 += __shfl_xor_sync(0xffffffffu, rs0, 2);
            rs1 += __shfl_xor_sync(0xffffffffu, rs1, 1);
            rs1 += __shfl_xor_sync(0xffffffffu, rs1, 2);
            l0 = l0 * corr0 + rs0;
            l1 = l1 * corr1 + rs1;
        }

        // ---- O += P V (P packed from sc registers)
#pragma unroll
        for (int s = 0; s < 4; ++s) {
            uint32_t af[4];
            af[0] = pack_h2(sc[2 * s][0],     sc[2 * s][1]);
            af[1] = pack_h2(sc[2 * s][2],     sc[2 * s][3]);
            af[2] = pack_h2(sc[2 * s + 1][0], sc[2 * s + 1][1]);
            af[3] = pack_h2(sc[2 * s + 1][2], sc[2 * s + 1][3]);
#pragma unroll
            for (int g = 0; g < 4; ++g) {
                int row = g * 16 + b_row_rel;
                uint32_t off = (uint32_t)(row * 128 + (2 * s + b_hi) * 16);
                uint32_t r0, r1, r2, r3;
                ldsm_x4(vb + sw128(off), r0, r1, r2, r3);
                uint32_t bf0[2] = { r0, r1 };
                uint32_t bf1[2] = { r2, r3 };
                mma_f16(oc[2 * g + 0], af, bf0);
                mma_f16(oc[2 * g + 1], af, bf1);
            }
        }

        __syncthreads();                   // all warps done reading buf
        if (kt + 3 < NKT) {
            issue_kv(kt + 3, buf);         // refill the buffer just freed
        }
        CP_COMMIT();
        if (kt + 1 < NKT) {
            CP_WAIT2();                    // tile kt+1 landed (2 may pend)
            __syncthreads();
        }
        buf = (buf == 2) ? 0 : buf + 1;
    }

    // ---- epilogue: ctx half [(q*B+b)*E + h*64 + col]
    const int tg = lane & 3;
    const float inv0 = 1.0f / l0;
    const float inv1 = 1.0f / l1;
    const int q0 = qt * AQ + wid * 16 + (lane >> 2);
#pragma unroll
    for (int n = 0; n < 8; ++n) {
        const int col = h * DH_ + n * 8 + 2 * tg;
        uint32_t lo = pack_h2(oc[n][0] * inv0, oc[n][1] * inv0);
        uint32_t hi = pack_h2(oc[n][2] * inv1, oc[n][3] * inv1);
        *(uint32_t*)(Ctx + (size_t)(q0 * 2 + b) * E_ + col) = lo;
        *(uint32_t*)(Ctx + (size_t)((q0 + 8) * 2 + b) * E_ + col) = hi;
    }
}

// ---------------------------------------------------------------------------
// Launcher (4 launches)
// ---------------------------------------------------------------------------
extern "C" void kernel_launch(void* const* d_in, const int* in_sizes, int n_in,
                              void* d_out, int out_size)
{
    const float* query = (const float*)d_in[0];
    const float* wq = (const float*)d_in[1];
    const float* bq = (const float*)d_in[2];
    const float* wk = (const float*)d_in[3];
    const float* bk = (const float*)d_in[4];
    const float* wv = (const float*)d_in[5];
    const float* bv = (const float*)d_in[6];
    const float* wo = (const float*)d_in[7];
    const float* bo = (const float*)d_in[8];
    float* out = (float*)d_out;

    __half *hx, *hwq, *hwk, *hwv, *hwo, *qb, *kb, *vtb, *cb;
    cudaGetSymbolAddress((void**)&hx,  g_hx);
    cudaGetSymbolAddress((void**)&hwq, g_hwq);
    cudaGetSymbolAddress((void**)&hwk, g_hwk);
    cudaGetSymbolAddress((void**)&hwv, g_hwv);
    cudaGetSymbolAddress((void**)&hwo, g_hwo);
    cudaGetSymbolAddress((void**)&qb,  g_q);
    cudaGetSymbolAddress((void**)&kb,  g_k);
    cudaGetSymbolAddress((void**)&vtb, g_vt);
    cudaGetSymbolAddress((void**)&cb,  g_ctx);

    cvt_all_f16<<<CVT_BLOCKS, 256>>>(query, wq, wk, wv, wo,
                                     hx, hwq, hwk, hwv, hwo);

    cudaFuncSetAttribute(gemm_qkv_f16, cudaFuncAttributeMaxDynamicSharedMemorySize, GEMM_SMEM);
    cudaFuncSetAttribute(gemm_out_f16, cudaFuncAttributeMaxDynamicSharedMemorySize, GEMM_SMEM);
    cudaFuncSetAttribute(attn_mma_f16, cudaFuncAttributeMaxDynamicSharedMemorySize, ASMEM);

    gemm_qkv_f16<<<dim3(E_ / 128, M_ / 128, 3), 256, GEMM_SMEM>>>(
        hx, hwq, hwk, hwv, bq, bk, bv, qb, kb, vtb);

    attn_mma_f16<<<dim3(S_ / AQ, H_, B_), 256, ASMEM>>>(qb, kb, vtb, cb);

    gemm_out_f16<<<dim3(E_ / 128, M_ / 128), 256, GEMM_SMEM>>>(cb, hwo, bo, out);
}